// round 5
// baseline (speedup 1.0000x reference)
#include <cuda_runtime.h>

// Problem constants (shapes fixed by dataset)
#define NMAX  50000
#define EMAX  1600000
#define RREL  8
#define INF   128
#define HIDF  64

// ---------------- scratch (static device globals; no allocs) ----------------
__device__ __align__(256) float g_xw[(size_t)RREL * NMAX * HIDF];  // per-relation transformed feats
__device__ __align__(256) float g_h[(size_t)NMAX * HIDF];          // layer-1 output accumulator
__device__ __align__(256) int   g_key[EMAX];                       // dst*8 + etype
__device__ __align__(256) int   g_cnt[NMAX * RREL];

// ---------------- f32x2 helpers (packed dual-FMA, sm_100+) ----------------
__device__ __forceinline__ unsigned long long pk2(float lo, float hi) {
    unsigned long long r;
    asm("mov.b64 %0, {%1, %2};" : "=l"(r)
        : "r"(__float_as_uint(lo)), "r"(__float_as_uint(hi)));
    return r;
}
__device__ __forceinline__ void up2(unsigned long long v, float& lo, float& hi) {
    unsigned int a, b;
    asm("mov.b64 {%0, %1}, %2;" : "=r"(a), "=r"(b) : "l"(v));
    lo = __uint_as_float(a);
    hi = __uint_as_float(b);
}
__device__ __forceinline__ void fma2(unsigned long long& d, unsigned long long a, unsigned long long b) {
    asm("fma.rn.f32x2 %0, %1, %2, %3;" : "=l"(d) : "l"(a), "l"(b), "l"(d));
}

// ---------------- kernel: zero counts ----------------
__global__ void k_zero_cnt(int* __restrict__ cnt, int n) {
    int i = blockIdx.x * blockDim.x + threadIdx.x;
    if (i < n) cnt[i] = 0;
}

// ---------------- kernel: edge prep (key + per-(dst,rel) counts) ----------------
// edge_index / edge_type are int32 (JAX x64 disabled downcasts int64 -> int32).
__global__ void k_prep(const int* __restrict__ ei, const int* __restrict__ et,
                       int* __restrict__ key, int* __restrict__ cnt, int E) {
    int e = blockIdx.x * blockDim.x + threadIdx.x;
    if (e >= E) return;
    int d = ei[E + e];          // dst row of edge_index [2, E]
    int t = et[e];
    int k = d * RREL + t;
    key[e] = k;
    atomicAdd(&cnt[k], 1);
}

// ---------------- kernel: batched skinny GEMM ----------------
// For m in [0,8]:  Y_m[n, 0:64] = act(X[n, 0:K]) @ W_m[0:K, 0:64] (+bias for m==8)
// m<8: W = Wrel[m], Y = Yrel + m*N*64; m==8: W = Wroot, Y = Yroot (+bias),
// which initializes the atomic accumulation target (no separate memset).
template<int K, bool RELU_IN>
__global__ void __launch_bounds__(256, 2) k_gemm(
    const float* __restrict__ X, const float* __restrict__ Wrel,
    const float* __restrict__ Wroot, const float* __restrict__ bias,
    float* __restrict__ Yrel, float* __restrict__ Yroot, int Nn)
{
    constexpr int BM = 128;
    constexpr int LD = K + 4;  // pad -> conflict-free strided A-reads
    extern __shared__ float smem[];
    float* Xs = smem;            // [BM][LD]
    float* Ws = smem + BM * LD;  // [K][64]

    const int m = blockIdx.y;
    const float* W = (m < RREL) ? (Wrel + m * K * 64) : Wroot;
    const int row0 = blockIdx.x * BM;
    const int tid = threadIdx.x;

    // Load X tile (guarded, optional ReLU), vectorized
#pragma unroll
    for (int it = 0; it < BM * K / 4 / 256; ++it) {
        int idx = tid + it * 256;
        int r = idx / (K / 4), c4 = idx % (K / 4);
        int grow = row0 + r;
        float4 v = make_float4(0.f, 0.f, 0.f, 0.f);
        if (grow < Nn) v = *(const float4*)(X + (size_t)grow * K + c4 * 4);
        if (RELU_IN) {
            v.x = fmaxf(v.x, 0.f); v.y = fmaxf(v.y, 0.f);
            v.z = fmaxf(v.z, 0.f); v.w = fmaxf(v.w, 0.f);
        }
        *(float4*)&Xs[r * LD + c4 * 4] = v;
    }
    // Load W tile
#pragma unroll
    for (int it = 0; it < K * 16 / 256; ++it) {
        int idx = tid + it * 256;
        int r = idx / 16, c4 = idx % 16;
        *(float4*)&Ws[r * 64 + c4 * 4] = *(const float4*)(W + r * 64 + c4 * 4);
    }
    __syncthreads();

    const int tx = tid & 7;        // 8 column groups of 8
    const int ty = tid >> 3;       // 32 row groups; rows ty + 32*i
    const int col = tx * 8;

    unsigned long long acc[4][4];  // 4 rows x 4 f32x2 (=8 cols)
#pragma unroll
    for (int i = 0; i < 4; i++)
#pragma unroll
        for (int p = 0; p < 4; p++) acc[i][p] = 0ULL;

#pragma unroll 2
    for (int k = 0; k < K; ++k) {
        unsigned long long aa[4];
#pragma unroll
        for (int i = 0; i < 4; i++) {
            float a = Xs[(ty + 32 * i) * LD + k];
            aa[i] = pk2(a, a);
        }
        float4 b0 = *(const float4*)&Ws[k * 64 + col];
        float4 b1 = *(const float4*)&Ws[k * 64 + col + 4];
        unsigned long long bb[4];
        bb[0] = pk2(b0.x, b0.y); bb[1] = pk2(b0.z, b0.w);
        bb[2] = pk2(b1.x, b1.y); bb[3] = pk2(b1.z, b1.w);
#pragma unroll
        for (int i = 0; i < 4; i++)
#pragma unroll
            for (int p = 0; p < 4; p++) fma2(acc[i][p], aa[i], bb[p]);
    }

    float* Y = (m < RREL) ? (Yrel + (size_t)m * Nn * 64) : Yroot;
    const bool useBias = (m == RREL);
    float bv[8];
    if (useBias) {
#pragma unroll
        for (int j = 0; j < 8; j++) bv[j] = bias[col + j];
    }
#pragma unroll
    for (int i = 0; i < 4; i++) {
        int grow = row0 + ty + 32 * i;
        if (grow < Nn) {
            float o[8];
#pragma unroll
            for (int p = 0; p < 4; p++) up2(acc[i][p], o[2 * p], o[2 * p + 1]);
            if (useBias) {
#pragma unroll
                for (int j = 0; j < 8; j++) o[j] += bv[j];
            }
            *(float4*)(Y + (size_t)grow * 64 + col)     = make_float4(o[0], o[1], o[2], o[3]);
            *(float4*)(Y + (size_t)grow * 64 + col + 4) = make_float4(o[4], o[5], o[6], o[7]);
        }
    }
}

// ---------------- kernel: edge gather + normalized scatter-add ----------------
// 16 threads per edge, one float4 each; vectorized L2 reduction (red.global.v4).
__global__ void k_edge(const int* __restrict__ ei, const int* __restrict__ key,
                       const int* __restrict__ cnt, const float* __restrict__ xw,
                       float* __restrict__ out, int E, int Nn)
{
    int gid = blockIdx.x * blockDim.x + threadIdx.x;
    int e = gid >> 4;
    if (e >= E) return;
    int j = (gid & 15) << 2;

    int k = key[e];
    int c = cnt[k];
    float inv = 1.0f / (float)(c > 0 ? c : 1);
    int s = ei[e];               // src row of edge_index [2, E]
    int t = k & (RREL - 1);
    int d = k >> 3;

    const float4 v = *(const float4*)(xw + ((size_t)t * Nn + s) * 64 + j);
    float* addr = out + (size_t)d * 64 + j;
    asm volatile("red.global.add.v4.f32 [%0], {%1,%2,%3,%4};"
                 :: "l"(addr), "f"(v.x * inv), "f"(v.y * inv), "f"(v.z * inv), "f"(v.w * inv)
                 : "memory");
}

// ---------------- launch ----------------
extern "C" void kernel_launch(void* const* d_in, const int* in_sizes, int n_in,
                              void* d_out, int out_size) {
    const float* x       = (const float*)d_in[0];
    const int*   ei      = (const int*)d_in[1];   // int32 (JAX x64 disabled)
    const int*   et      = (const int*)d_in[2];   // int32
    const float* W1_rel  = (const float*)d_in[3];
    const float* W1_root = (const float*)d_in[4];
    const float* b1      = (const float*)d_in[5];
    const float* W2_rel  = (const float*)d_in[6];
    const float* W2_root = (const float*)d_in[7];
    const float* b2      = (const float*)d_in[8];
    float* out = (float*)d_out;

    const int N = in_sizes[0] / INF;
    const int E = in_sizes[2];

    float *xw, *h;
    int *key, *cnt;
    cudaGetSymbolAddress((void**)&xw,  g_xw);
    cudaGetSymbolAddress((void**)&h,   g_h);
    cudaGetSymbolAddress((void**)&key, g_key);
    cudaGetSymbolAddress((void**)&cnt, g_cnt);

    const int smem1 = (128 * (128 + 4) + 128 * 64) * 4;  // 100352 B
    const int smem2 = (128 * (64 + 4)  +  64 * 64) * 4;  //  51200 B
    cudaFuncSetAttribute(k_gemm<128, false>, cudaFuncAttributeMaxDynamicSharedMemorySize, smem1);
    cudaFuncSetAttribute(k_gemm<64,  true>,  cudaFuncAttributeMaxDynamicSharedMemorySize, smem2);

    // edge prep + per-(dst,rel) counts
    k_zero_cnt<<<(N * RREL + 255) / 256, 256>>>(cnt, N * RREL);
    k_prep<<<(E + 255) / 256, 256>>>(ei, et, key, cnt, E);

    dim3 gg((N + 127) / 128, RREL + 1);
    long long tot = (long long)E * 16;
    int eb = (int)((tot + 255) / 256);

    // Layer 1: transforms (+ root+bias init of h), then edge aggregation into h
    k_gemm<128, false><<<gg, 256, smem1>>>(x, W1_rel, W1_root, b1, xw, h, N);
    k_edge<<<eb, 256>>>(ei, key, cnt, xw, h, E, N);

    // Layer 2: ReLU fused into GEMM loads; root init of d_out; edge aggregation into d_out
    k_gemm<64, true><<<gg, 256, smem2>>>(h, W2_rel, W2_root, b2, xw, out, N);
    k_edge<<<eb, 256>>>(ei, key, cnt, xw, out, E, N);
}

// round 6
// speedup vs baseline: 1.1822x; 1.1822x over previous
#include <cuda_runtime.h>

// Problem constants (shapes fixed by dataset)
#define NMAX  50000
#define EMAX  1600000
#define RREL  8
#define INF   128
#define HIDF  64

// ---------------- scratch (static device globals; no allocs) ----------------
__device__ __align__(256) float g_xw[(size_t)RREL * NMAX * HIDF];  // per-relation transformed feats
__device__ __align__(256) float g_h[(size_t)NMAX * HIDF];          // layer-1 output accumulator
__device__ __align__(256) int   g_cnt[NMAX * RREL];
__device__ __align__(256) int4  g_epack[EMAX];                     // {gatherOff, scatterOff, inv(bits), 0}

// ---------------- f32x2 helpers (packed dual-FMA, sm_100+) ----------------
__device__ __forceinline__ unsigned long long pk2(float lo, float hi) {
    unsigned long long r;
    asm("mov.b64 %0, {%1, %2};" : "=l"(r)
        : "r"(__float_as_uint(lo)), "r"(__float_as_uint(hi)));
    return r;
}
__device__ __forceinline__ void up2(unsigned long long v, float& lo, float& hi) {
    unsigned int a, b;
    asm("mov.b64 {%0, %1}, %2;" : "=r"(a), "=r"(b) : "l"(v));
    lo = __uint_as_float(a);
    hi = __uint_as_float(b);
}
__device__ __forceinline__ void fma2(unsigned long long& d, unsigned long long a, unsigned long long b) {
    asm("fma.rn.f32x2 %0, %1, %2, %3;" : "=l"(d) : "l"(a), "l"(b), "l"(d));
}

// ---------------- kernel: zero counts ----------------
__global__ void k_zero_cnt(int* __restrict__ cnt, int n) {
    int i = blockIdx.x * blockDim.x + threadIdx.x;
    if (i < n) cnt[i] = 0;
}

// ---------------- kernel: per-(dst,rel) counts ----------------
__global__ void k_count(const int* __restrict__ ei, const int* __restrict__ et,
                        int* __restrict__ cnt, int E) {
    int e = blockIdx.x * blockDim.x + threadIdx.x;
    if (e >= E) return;
    atomicAdd(&cnt[ei[E + e] * RREL + et[e]], 1);
}

// ---------------- kernel: build per-edge descriptor ----------------
// pack = { (t*N + s)*64, d*64, bits(1/max(cnt,1)), 0 }
__global__ void k_pack(const int* __restrict__ ei, const int* __restrict__ et,
                       const int* __restrict__ cnt, int4* __restrict__ pack,
                       int E, int Nn) {
    int e = blockIdx.x * blockDim.x + threadIdx.x;
    if (e >= E) return;
    int s = ei[e];
    int d = ei[E + e];
    int t = et[e];
    int c = cnt[d * RREL + t];
    float inv = 1.0f / (float)(c > 0 ? c : 1);
    pack[e] = make_int4((t * Nn + s) * 64, d * 64, __float_as_int(inv), 0);
}

// ---------------- kernel: batched skinny GEMM ----------------
// For m in [0,8]:  Y_m[n, 0:64] = act(X[n, 0:K]) @ W_m[0:K, 0:64] (+bias for m==8)
// m<8: W = Wrel[m], Y = Yrel + m*N*64; m==8: W = Wroot, Y = Yroot (+bias),
// which initializes the atomic accumulation target (no separate memset).
template<int K, bool RELU_IN>
__global__ void __launch_bounds__(256, 2) k_gemm(
    const float* __restrict__ X, const float* __restrict__ Wrel,
    const float* __restrict__ Wroot, const float* __restrict__ bias,
    float* __restrict__ Yrel, float* __restrict__ Yroot, int Nn)
{
    constexpr int BM = 128;
    constexpr int LD = K + 4;  // pad (4 floats) keeps rows 16B-aligned & conflict-free
    extern __shared__ float smem[];
    float* Xs = smem;            // [BM][LD]
    float* Ws = smem + BM * LD;  // [K][64]

    const int m = blockIdx.y;
    const float* W = (m < RREL) ? (Wrel + m * K * 64) : Wroot;
    const int row0 = blockIdx.x * BM;
    const int tid = threadIdx.x;

    // Load X tile (guarded, optional ReLU), vectorized
#pragma unroll
    for (int it = 0; it < BM * K / 4 / 256; ++it) {
        int idx = tid + it * 256;
        int r = idx / (K / 4), c4 = idx % (K / 4);
        int grow = row0 + r;
        float4 v = make_float4(0.f, 0.f, 0.f, 0.f);
        if (grow < Nn) v = *(const float4*)(X + (size_t)grow * K + c4 * 4);
        if (RELU_IN) {
            v.x = fmaxf(v.x, 0.f); v.y = fmaxf(v.y, 0.f);
            v.z = fmaxf(v.z, 0.f); v.w = fmaxf(v.w, 0.f);
        }
        *(float4*)&Xs[r * LD + c4 * 4] = v;
    }
    // Load W tile
#pragma unroll
    for (int it = 0; it < K * 16 / 256; ++it) {
        int idx = tid + it * 256;
        int r = idx / 16, c4 = idx % 16;
        *(float4*)&Ws[r * 64 + c4 * 4] = *(const float4*)(W + r * 64 + c4 * 4);
    }
    __syncthreads();

    const int tx = tid & 7;        // 8 column groups of 8
    const int ty = tid >> 3;       // 32 row groups; rows ty + 32*i
    const int col = tx * 8;

    unsigned long long acc[4][4];  // 4 rows x 4 f32x2 (=8 cols)
#pragma unroll
    for (int i = 0; i < 4; i++)
#pragma unroll
        for (int p = 0; p < 4; p++) acc[i][p] = 0ULL;

    for (int k = 0; k < K; k += 4) {
        // A: one float4 per row covers 4 k-steps (k contiguous in Xs)
        float4 a4[4];
#pragma unroll
        for (int i = 0; i < 4; i++)
            a4[i] = *(const float4*)&Xs[(ty + 32 * i) * LD + k];
#pragma unroll
        for (int kk = 0; kk < 4; ++kk) {
            float4 b0 = *(const float4*)&Ws[(k + kk) * 64 + col];
            float4 b1 = *(const float4*)&Ws[(k + kk) * 64 + col + 4];
            unsigned long long bb[4];
            bb[0] = pk2(b0.x, b0.y); bb[1] = pk2(b0.z, b0.w);
            bb[2] = pk2(b1.x, b1.y); bb[3] = pk2(b1.z, b1.w);
            const float* af = (const float*)a4;
#pragma unroll
            for (int i = 0; i < 4; i++) {
                float av = af[i * 4 + kk];
                unsigned long long aa = pk2(av, av);
#pragma unroll
                for (int p = 0; p < 4; p++) fma2(acc[i][p], aa, bb[p]);
            }
        }
    }

    float* Y = (m < RREL) ? (Yrel + (size_t)m * Nn * 64) : Yroot;
    const bool useBias = (m == RREL);
    float bv[8];
    if (useBias) {
#pragma unroll
        for (int j = 0; j < 8; j++) bv[j] = bias[col + j];
    }
#pragma unroll
    for (int i = 0; i < 4; i++) {
        int grow = row0 + ty + 32 * i;
        if (grow < Nn) {
            float o[8];
#pragma unroll
            for (int p = 0; p < 4; p++) up2(acc[i][p], o[2 * p], o[2 * p + 1]);
            if (useBias) {
#pragma unroll
                for (int j = 0; j < 8; j++) o[j] += bv[j];
            }
            *(float4*)(Y + (size_t)grow * 64 + col)     = make_float4(o[0], o[1], o[2], o[3]);
            *(float4*)(Y + (size_t)grow * 64 + col + 4) = make_float4(o[4], o[5], o[6], o[7]);
        }
    }
}

// ---------------- kernel: edge gather + normalized scatter-add ----------------
// 16 threads/edge; all 16 lanes read the SAME 16B descriptor (one broadcast
// wavefront per warp), then one float4 gather + one red.global.add.v4 each.
__global__ void __launch_bounds__(256) k_edge(
    const int4* __restrict__ pack, const float* __restrict__ xw,
    float* __restrict__ out, int E)
{
    int gid = blockIdx.x * blockDim.x + threadIdx.x;
    int e = gid >> 4;
    if (e >= E) return;
    int j = (gid & 15) << 2;

    const int4 p = __ldg(&pack[e]);
    const float inv = __int_as_float(p.z);

    const float4 v = __ldg((const float4*)(xw + p.x + j));
    float* addr = out + p.y + j;
    asm volatile("red.global.add.v4.f32 [%0], {%1,%2,%3,%4};"
                 :: "l"(addr), "f"(v.x * inv), "f"(v.y * inv), "f"(v.z * inv), "f"(v.w * inv)
                 : "memory");
}

// ---------------- launch ----------------
extern "C" void kernel_launch(void* const* d_in, const int* in_sizes, int n_in,
                              void* d_out, int out_size) {
    const float* x       = (const float*)d_in[0];
    const int*   ei      = (const int*)d_in[1];   // int32 (JAX x64 disabled)
    const int*   et      = (const int*)d_in[2];   // int32
    const float* W1_rel  = (const float*)d_in[3];
    const float* W1_root = (const float*)d_in[4];
    const float* b1      = (const float*)d_in[5];
    const float* W2_rel  = (const float*)d_in[6];
    const float* W2_root = (const float*)d_in[7];
    const float* b2      = (const float*)d_in[8];
    float* out = (float*)d_out;

    const int N = in_sizes[0] / INF;
    const int E = in_sizes[2];

    float *xw, *h;
    int *cnt;
    int4 *pack;
    cudaGetSymbolAddress((void**)&xw,   g_xw);
    cudaGetSymbolAddress((void**)&h,    g_h);
    cudaGetSymbolAddress((void**)&cnt,  g_cnt);
    cudaGetSymbolAddress((void**)&pack, g_epack);

    const int smem1 = (128 * (128 + 4) + 128 * 64) * 4;  // 100352 B
    const int smem2 = (128 * (64 + 4)  +  64 * 64) * 4;  //  51200 B
    cudaFuncSetAttribute(k_gemm<128, false>, cudaFuncAttributeMaxDynamicSharedMemorySize, smem1);
    cudaFuncSetAttribute(k_gemm<64,  true>,  cudaFuncAttributeMaxDynamicSharedMemorySize, smem2);

    // edge prep: counts, then per-edge descriptor
    k_zero_cnt<<<(N * RREL + 255) / 256, 256>>>(cnt, N * RREL);
    k_count<<<(E + 255) / 256, 256>>>(ei, et, cnt, E);
    k_pack<<<(E + 255) / 256, 256>>>(ei, et, cnt, pack, E, N);

    dim3 gg((N + 127) / 128, RREL + 1);
    long long tot = (long long)E * 16;
    int eb = (int)((tot + 255) / 256);

    // Layer 1: transforms (+ root+bias init of h), then edge aggregation into h
    k_gemm<128, false><<<gg, 256, smem1>>>(x, W1_rel, W1_root, b1, xw, h, N);
    k_edge<<<eb, 256>>>(pack, xw, h, E);

    // Layer 2: ReLU fused into GEMM loads; root init of d_out; edge aggregation into d_out
    k_gemm<64, true><<<gg, 256, smem2>>>(h, W2_rel, W2_root, b2, xw, out, N);
    k_edge<<<eb, 256>>>(pack, xw, out, E);
}

// round 7
// speedup vs baseline: 1.5159x; 1.2823x over previous
#include <cuda_runtime.h>

// Problem constants (shapes fixed by dataset)
#define NMAX  50000
#define EMAX  1600000
#define RREL  8
#define INF   128
#define HIDF  64

// ---------------- scratch (static device globals; no allocs) ----------------
__device__ __align__(256) float g_xw[(size_t)RREL * NMAX * HIDF];  // per-relation transformed feats
__device__ __align__(256) float g_h[(size_t)NMAX * HIDF];          // layer-1 output accumulator
__device__ __align__(256) int   g_cnt[NMAX * RREL];
__device__ __align__(256) int4  g_epack[EMAX];                     // {gatherOff, scatterOff, inv(bits), 0}

// ---------------- f32x2 helpers (packed dual-FMA, sm_100+) ----------------
__device__ __forceinline__ unsigned long long pk2(float lo, float hi) {
    unsigned long long r;
    asm("mov.b64 %0, {%1, %2};" : "=l"(r)
        : "r"(__float_as_uint(lo)), "r"(__float_as_uint(hi)));
    return r;
}
__device__ __forceinline__ void up2(unsigned long long v, float& lo, float& hi) {
    unsigned int a, b;
    asm("mov.b64 {%0, %1}, %2;" : "=r"(a), "=r"(b) : "l"(v));
    lo = __uint_as_float(a);
    hi = __uint_as_float(b);
}
__device__ __forceinline__ void fma2(unsigned long long& d, unsigned long long a, unsigned long long b) {
    asm("fma.rn.f32x2 %0, %1, %2, %3;" : "=l"(d) : "l"(a), "l"(b), "l"(d));
}

// ---------------- kernel: zero counts ----------------
__global__ void k_zero_cnt(int* __restrict__ cnt, int n) {
    int i = blockIdx.x * blockDim.x + threadIdx.x;
    if (i < n) cnt[i] = 0;
}

// ---------------- kernel: per-(dst,rel) counts ----------------
__global__ void k_count(const int* __restrict__ ei, const int* __restrict__ et,
                        int* __restrict__ cnt, int E) {
    int e = blockIdx.x * blockDim.x + threadIdx.x;
    if (e >= E) return;
    atomicAdd(&cnt[ei[E + e] * RREL + et[e]], 1);
}

// ---------------- kernel: build per-edge descriptor ----------------
// pack = { (t*N + s)*64, d*64, bits(1/max(cnt,1)), 0 }
__global__ void k_pack(const int* __restrict__ ei, const int* __restrict__ et,
                       const int* __restrict__ cnt, int4* __restrict__ pack,
                       int E, int Nn) {
    int e = blockIdx.x * blockDim.x + threadIdx.x;
    if (e >= E) return;
    int s = ei[e];
    int d = ei[E + e];
    int t = et[e];
    int c = cnt[d * RREL + t];
    float inv = 1.0f / (float)(c > 0 ? c : 1);
    pack[e] = make_int4((t * Nn + s) * 64, d * 64, __float_as_int(inv), 0);
}

// ---------------- kernel: batched skinny GEMM ----------------
// For m in [0,8]:  Y_m[n, 0:64] = act(X[n, 0:K]) @ W_m[0:K, 0:64] (+bias for m==8)
// m<8: W = Wrel[m], Y = Yrel + m*N*64; m==8: W = Wroot, Y = Yroot (+bias).
// BM=256 rows/block, 256 threads, 8x8 micro-tile, K chunked by 32.
// Thread cols: {tx*4..tx*4+3, 32+tx*4..32+tx*4+3} -> warp's B-reads tile one
// 128B Ws row exactly (conflict-free). A-reads broadcast across tx.
template<int K, bool RELU_IN>
__global__ void __launch_bounds__(256, 2) k_gemm(
    const float* __restrict__ X, const float* __restrict__ Wrel,
    const float* __restrict__ Wroot, const float* __restrict__ bias,
    float* __restrict__ Yrel, float* __restrict__ Yroot, int Nn)
{
    constexpr int BM = 256;
    constexpr int KC = 32;
    constexpr int LDX = KC + 4;     // 36: conflict-free row stride, 16B-aligned
    constexpr int NCHUNK = K / KC;

    __shared__ float Xs[BM * LDX];  // 36 KB
    __shared__ float Ws[KC * 64];   //  8 KB

    const int m = blockIdx.y;
    const float* W = (m < RREL) ? (Wrel + m * K * 64) : Wroot;
    const int row0 = blockIdx.x * BM;
    const int tid = threadIdx.x;
    const int tx = tid & 7;         // 8 column groups
    const int ty = tid >> 3;        // 32 row groups; rows ty + 32*i, i<8
    const int colA = tx * 4;        // cols [colA, colA+4) and [colA+32, colA+36)

    unsigned long long acc[8][4];   // 8 rows x 4 f32x2 (=8 cols)
#pragma unroll
    for (int i = 0; i < 8; i++)
#pragma unroll
        for (int p = 0; p < 4; p++) acc[i][p] = 0ULL;

    for (int kc = 0; kc < NCHUNK; ++kc) {
        if (kc) __syncthreads();
        // Load X chunk: 256 rows x 32 floats (8 float4 / thread)
#pragma unroll
        for (int it = 0; it < 8; ++it) {
            int idx = tid + it * 256;
            int r = idx >> 3, c4 = idx & 7;
            int grow = row0 + r;
            float4 v = make_float4(0.f, 0.f, 0.f, 0.f);
            if (grow < Nn) v = *(const float4*)(X + (size_t)grow * K + kc * KC + c4 * 4);
            if (RELU_IN) {
                v.x = fmaxf(v.x, 0.f); v.y = fmaxf(v.y, 0.f);
                v.z = fmaxf(v.z, 0.f); v.w = fmaxf(v.w, 0.f);
            }
            *(float4*)&Xs[r * LDX + c4 * 4] = v;
        }
        // Load W chunk: 32 x 64 floats (2 float4 / thread)
#pragma unroll
        for (int it = 0; it < 2; ++it) {
            int idx = tid + it * 256;
            int r = idx >> 4, c4 = idx & 15;
            *(float4*)&Ws[r * 64 + c4 * 4] =
                *(const float4*)(W + (size_t)(kc * KC + r) * 64 + c4 * 4);
        }
        __syncthreads();

#pragma unroll 8
        for (int k = 0; k < KC; ++k) {
            float4 b0 = *(const float4*)&Ws[k * 64 + colA];
            float4 b1 = *(const float4*)&Ws[k * 64 + 32 + colA];
            unsigned long long bb[4];
            bb[0] = pk2(b0.x, b0.y); bb[1] = pk2(b0.z, b0.w);
            bb[2] = pk2(b1.x, b1.y); bb[3] = pk2(b1.z, b1.w);
#pragma unroll
            for (int i = 0; i < 8; i++) {
                float a = Xs[(ty + 32 * i) * LDX + k];
                unsigned long long aa = pk2(a, a);
#pragma unroll
                for (int p = 0; p < 4; p++) fma2(acc[i][p], aa, bb[p]);
            }
        }
    }

    float* Y = (m < RREL) ? (Yrel + (size_t)m * Nn * 64) : Yroot;
    const bool useBias = (m == RREL);
    float bv[8];
    if (useBias) {
#pragma unroll
        for (int j = 0; j < 4; j++) { bv[j] = bias[colA + j]; bv[4 + j] = bias[32 + colA + j]; }
    }
#pragma unroll
    for (int i = 0; i < 8; i++) {
        int grow = row0 + ty + 32 * i;
        if (grow < Nn) {
            float o[8];
#pragma unroll
            for (int p = 0; p < 4; p++) up2(acc[i][p], o[2 * p], o[2 * p + 1]);
            if (useBias) {
#pragma unroll
                for (int j = 0; j < 8; j++) o[j] += bv[j];
            }
            *(float4*)(Y + (size_t)grow * 64 + colA)      = make_float4(o[0], o[1], o[2], o[3]);
            *(float4*)(Y + (size_t)grow * 64 + 32 + colA) = make_float4(o[4], o[5], o[6], o[7]);
        }
    }
}

// ---------------- kernel: edge gather + normalized scatter-add ----------------
// 16 threads/edge; all 16 lanes read the SAME 16B descriptor (one broadcast
// wavefront per warp), then one float4 gather + one red.global.add.v4 each.
__global__ void __launch_bounds__(256) k_edge(
    const int4* __restrict__ pack, const float* __restrict__ xw,
    float* __restrict__ out, int E)
{
    int gid = blockIdx.x * blockDim.x + threadIdx.x;
    int e = gid >> 4;
    if (e >= E) return;
    int j = (gid & 15) << 2;

    const int4 p = __ldg(&pack[e]);
    const float inv = __int_as_float(p.z);

    const float4 v = __ldg((const float4*)(xw + p.x + j));
    float* addr = out + p.y + j;
    asm volatile("red.global.add.v4.f32 [%0], {%1,%2,%3,%4};"
                 :: "l"(addr), "f"(v.x * inv), "f"(v.y * inv), "f"(v.z * inv), "f"(v.w * inv)
                 : "memory");
}

// ---------------- launch ----------------
extern "C" void kernel_launch(void* const* d_in, const int* in_sizes, int n_in,
                              void* d_out, int out_size) {
    const float* x       = (const float*)d_in[0];
    const int*   ei      = (const int*)d_in[1];   // int32 (JAX x64 disabled)
    const int*   et      = (const int*)d_in[2];   // int32
    const float* W1_rel  = (const float*)d_in[3];
    const float* W1_root = (const float*)d_in[4];
    const float* b1      = (const float*)d_in[5];
    const float* W2_rel  = (const float*)d_in[6];
    const float* W2_root = (const float*)d_in[7];
    const float* b2      = (const float*)d_in[8];
    float* out = (float*)d_out;

    const int N = in_sizes[0] / INF;
    const int E = in_sizes[2];

    float *xw, *h;
    int *cnt;
    int4 *pack;
    cudaGetSymbolAddress((void**)&xw,   g_xw);
    cudaGetSymbolAddress((void**)&h,    g_h);
    cudaGetSymbolAddress((void**)&cnt,  g_cnt);
    cudaGetSymbolAddress((void**)&pack, g_epack);

    // edge prep: counts, then per-edge descriptor
    k_zero_cnt<<<(N * RREL + 255) / 256, 256>>>(cnt, N * RREL);
    k_count<<<(E + 255) / 256, 256>>>(ei, et, cnt, E);
    k_pack<<<(E + 255) / 256, 256>>>(ei, et, cnt, pack, E, N);

    dim3 gg((N + 255) / 256, RREL + 1);
    long long tot = (long long)E * 16;
    int eb = (int)((tot + 255) / 256);

    // Layer 1: transforms (+ root+bias init of h), then edge aggregation into h
    k_gemm<128, false><<<gg, 256>>>(x, W1_rel, W1_root, b1, xw, h, N);
    k_edge<<<eb, 256>>>(pack, xw, h, E);

    // Layer 2: ReLU fused into GEMM loads; root init of d_out; edge aggregation into d_out
    k_gemm<64, true><<<gg, 256>>>(h, W2_rel, W2_root, b2, xw, out, N);
    k_edge<<<eb, 256>>>(pack, xw, out, E);
}

// round 9
// speedup vs baseline: 1.9156x; 1.2636x over previous
#include <cuda_runtime.h>
#include <cuda_bf16.h>
#include <cstdint>

// Problem constants (shapes fixed by dataset)
#define NMAX  50000
#define EMAX  1600000
#define RREL  8
#define INF   128

// ---------------- scratch (static device globals; no allocs) ----------------
__device__ __align__(256) float g_xw[(size_t)RREL * NMAX * 64];
__device__ __align__(256) float g_h[(size_t)NMAX * 64];
__device__ __align__(256) int   g_cnt[NMAX * RREL];
__device__ __align__(256) int4  g_epack[EMAX];
__device__ __align__(256) __nv_bfloat16 g_xhi[(size_t)NMAX * INF];
__device__ __align__(256) __nv_bfloat16 g_xlo[(size_t)NMAX * INF];
__device__ __align__(256) __nv_bfloat16 g_bhi1[9 * 64 * 128];
__device__ __align__(256) __nv_bfloat16 g_blo1[9 * 64 * 128];
__device__ __align__(256) __nv_bfloat16 g_bhi2[9 * 64 * 64];
__device__ __align__(256) __nv_bfloat16 g_blo2[9 * 64 * 64];

__device__ __forceinline__ uint32_t smem_u32(const void* p) {
    uint32_t a;
    asm("{ .reg .u64 t; cvta.to.shared.u64 t, %1; cvt.u32.u64 %0, t; }" : "=r"(a) : "l"(p));
    return a;
}
__device__ __forceinline__ void ldsm4(uint32_t* r, uint32_t addr) {
    asm volatile("ldmatrix.sync.aligned.m8n8.x4.shared.b16 {%0,%1,%2,%3}, [%4];"
                 : "=r"(r[0]), "=r"(r[1]), "=r"(r[2]), "=r"(r[3]) : "r"(addr));
}
__device__ __forceinline__ void mma16816(float* c, const uint32_t* a, uint32_t b0, uint32_t b1) {
    asm volatile(
        "mma.sync.aligned.m16n8k16.row.col.f32.bf16.bf16.f32 "
        "{%0,%1,%2,%3}, {%4,%5,%6,%7}, {%8,%9}, {%0,%1,%2,%3};"
        : "+f"(c[0]), "+f"(c[1]), "+f"(c[2]), "+f"(c[3])
        : "r"(a[0]), "r"(a[1]), "r"(a[2]), "r"(a[3]), "r"(b0), "r"(b1));
}

// ---------------- small prep kernels ----------------
__global__ void k_zero_cnt(int* __restrict__ cnt, int n) {
    int i = blockIdx.x * blockDim.x + threadIdx.x;
    if (i < n) cnt[i] = 0;
}
__global__ void k_count(const int* __restrict__ ei, const int* __restrict__ et,
                        int* __restrict__ cnt, int E) {
    int e = blockIdx.x * blockDim.x + threadIdx.x;
    if (e >= E) return;
    atomicAdd(&cnt[ei[E + e] * RREL + et[e]], 1);
}
__global__ void k_pack(const int* __restrict__ ei, const int* __restrict__ et,
                       const int* __restrict__ cnt, int4* __restrict__ pack,
                       int E, int Nn) {
    int e = blockIdx.x * blockDim.x + threadIdx.x;
    if (e >= E) return;
    int s = ei[e];
    int d = ei[E + e];
    int t = et[e];
    int c = cnt[d * RREL + t];
    float inv = 1.0f / (float)(c > 0 ? c : 1);
    pack[e] = make_int4((t * Nn + s) * 64, d * 64, __float_as_int(inv), 0);
}

// ---------------- fp32 -> bf16 hi/lo split (optionally fused ReLU) ----------------
template<bool RELU>
__global__ void k_split(const float* __restrict__ src, __nv_bfloat16* __restrict__ hi,
                        __nv_bfloat16* __restrict__ lo, int n) {
    int i = blockIdx.x * blockDim.x + threadIdx.x;
    int i4 = i * 4;
    if (i4 >= n) return;
    float4 v = *(const float4*)(src + i4);
    if (RELU) {
        v.x = fmaxf(v.x, 0.f); v.y = fmaxf(v.y, 0.f);
        v.z = fmaxf(v.z, 0.f); v.w = fmaxf(v.w, 0.f);
    }
    float vv[4] = {v.x, v.y, v.z, v.w};
    __nv_bfloat16 h[4], l[4];
#pragma unroll
    for (int j = 0; j < 4; j++) {
        h[j] = __float2bfloat16_rn(vv[j]);
        l[j] = __float2bfloat16_rn(vv[j] - __bfloat162float(h[j]));
    }
    ((__nv_bfloat162*)hi)[i * 2]     = __nv_bfloat162(h[0], h[1]);
    ((__nv_bfloat162*)hi)[i * 2 + 1] = __nv_bfloat162(h[2], h[3]);
    ((__nv_bfloat162*)lo)[i * 2]     = __nv_bfloat162(l[0], l[1]);
    ((__nv_bfloat162*)lo)[i * 2 + 1] = __nv_bfloat162(l[2], l[3]);
}

// ---------------- weight transpose+split: Bt[m][n][k] = W_m[k][n] ----------------
__global__ void k_splitw(const float* __restrict__ Wrel, const float* __restrict__ Wroot,
                         __nv_bfloat16* __restrict__ hi, __nv_bfloat16* __restrict__ lo, int K) {
    int idx = blockIdx.x * blockDim.x + threadIdx.x;
    if (idx >= 9 * 64 * K) return;
    int m = idx / (64 * K);
    int r = idx % (64 * K);
    int n = r / K;
    int k = r % K;
    float w = (m < RREL) ? Wrel[(size_t)m * K * 64 + k * 64 + n] : Wroot[k * 64 + n];
    __nv_bfloat16 h = __float2bfloat16_rn(w);
    hi[idx] = h;
    lo[idx] = __float2bfloat16_rn(w - __bfloat162float(h));
}

// ---------------- HMMA batched skinny GEMM (mma.sync, bf16 3-term split) --------
// For m in [0,8]: Y_m[n,0:64] = X[n,0:K] @ W_m (+bias for m==8).
// Block: 128 rows x 64 cols, 256 threads (8 warps x 16 rows), K chunked by 64.
// smem tiles padded to stride 72 bf16 (144B) -> ldmatrix conflict-free.
template<int K>
__global__ void __launch_bounds__(256) k_mma(
    const __nv_bfloat16* __restrict__ Ahi, const __nv_bfloat16* __restrict__ Alo,
    const __nv_bfloat16* __restrict__ Bhi, const __nv_bfloat16* __restrict__ Blo,
    const float* __restrict__ bias, float* __restrict__ Yrel, float* __restrict__ Yroot,
    int Nn)
{
    constexpr int KC  = 64;
    constexpr int LDB = KC + 8;                 // 72 bf16 = 144B row stride
    constexpr int NCH = K / KC;
    // smem element offsets (bf16)
    constexpr int OAH = 0;
    constexpr int OAL = 128 * LDB;
    constexpr int OBH = 2 * 128 * LDB;
    constexpr int OBL = 2 * 128 * LDB + 64 * LDB;

    extern __shared__ __nv_bfloat16 sm[];
    const uint32_t sb = smem_u32(sm);
    const int tid = threadIdx.x;
    const int w   = tid >> 5;
    const int l   = tid & 31;
    const int m   = blockIdx.y;
    const int row0 = blockIdx.x * 128;

    const __nv_bfloat16* bh = Bhi + (size_t)m * 64 * K;
    const __nv_bfloat16* bl = Blo + (size_t)m * 64 * K;

    // ldmatrix lane address bases (bytes, within smem tile)
    // A (m16k16): lanes 0-7 rows r0-7 @k0 | 8-15 rows r8-15 @k0 | 16-23 r0-7 @k8 | 24-31 r8-15 @k8
    const int arow = w * 16 + (l & 15);
    const int acol = (l >> 4) << 3;
    const uint32_t aoffA = (uint32_t)(arow * LDB + acol) * 2;
    // B (n-major): lanes 0-7 n0-7 @k0 | 8-15 n0-7 @k8 | 16-23 n8-15 @k0 | 24-31 n8-15 @k8
    const int brow = (l & 7) + ((l >> 4) << 3);
    const int bcol = ((l >> 3) & 1) << 3;
    const uint32_t aoffB = (uint32_t)(brow * LDB + bcol) * 2;

    float acc[8][4];
#pragma unroll
    for (int nb = 0; nb < 8; nb++)
#pragma unroll
        for (int j = 0; j < 4; j++) acc[nb][j] = 0.f;

    for (int kc = 0; kc < NCH; ++kc) {
        if (kc) __syncthreads();
        // load A chunk: 128 x 64 bf16, hi+lo (4 uint4 per thread per term)
#pragma unroll
        for (int it = 0; it < 4; ++it) {
            int idx = tid + it * 256;
            int r = idx >> 3, c8 = (idx & 7) << 3;
            int grow = row0 + r;
            uint4 vh = make_uint4(0, 0, 0, 0), vl = make_uint4(0, 0, 0, 0);
            if (grow < Nn) {
                vh = *(const uint4*)(Ahi + (size_t)grow * K + kc * KC + c8);
                vl = *(const uint4*)(Alo + (size_t)grow * K + kc * KC + c8);
            }
            *(uint4*)&sm[OAH + r * LDB + c8] = vh;
            *(uint4*)&sm[OAL + r * LDB + c8] = vl;
        }
        // load B chunk: 64 x 64 bf16, hi+lo (2 uint4 per thread per term)
#pragma unroll
        for (int it = 0; it < 2; ++it) {
            int idx = tid + it * 256;
            int r = idx >> 3, c8 = (idx & 7) << 3;
            *(uint4*)&sm[OBH + r * LDB + c8] = *(const uint4*)(bh + (size_t)r * K + kc * KC + c8);
            *(uint4*)&sm[OBL + r * LDB + c8] = *(const uint4*)(bl + (size_t)r * K + kc * KC + c8);
        }
        __syncthreads();

#pragma unroll
        for (int ks = 0; ks < KC / 16; ++ks) {
            const uint32_t kb = ks * 32;  // 16 bf16 = 32 bytes
            uint32_t ah[4], al[4];
            ldsm4(ah, sb + (OAH * 2) + aoffA + kb);
            ldsm4(al, sb + (OAL * 2) + aoffA + kb);
#pragma unroll
            for (int p = 0; p < 4; ++p) {   // n-block pairs: n = 16p
                uint32_t bhf[4], blf[4];
                const uint32_t bo = (uint32_t)(p * 16 * LDB) * 2 + kb;
                ldsm4(bhf, sb + (OBH * 2) + aoffB + bo);
                ldsm4(blf, sb + (OBL * 2) + aoffB + bo);
                mma16816(acc[2 * p],     ah, bhf[0], bhf[1]);
                mma16816(acc[2 * p + 1], ah, bhf[2], bhf[3]);
                mma16816(acc[2 * p],     ah, blf[0], blf[1]);
                mma16816(acc[2 * p + 1], ah, blf[2], blf[3]);
                mma16816(acc[2 * p],     al, bhf[0], bhf[1]);
                mma16816(acc[2 * p + 1], al, bhf[2], bhf[3]);
            }
        }
    }

    // epilogue
    float* Y = (m < RREL) ? (Yrel + (size_t)m * Nn * 64) : Yroot;
    const bool useBias = (m == RREL);
    const int rA = row0 + w * 16 + (l >> 2);
    const int c0 = (l & 3) * 2;
#pragma unroll
    for (int nb = 0; nb < 8; ++nb) {
        int col = nb * 8 + c0;
        float bx = 0.f, by = 0.f;
        if (useBias) { bx = bias[col]; by = bias[col + 1]; }
        if (rA < Nn)
            *(float2*)(Y + (size_t)rA * 64 + col) = make_float2(acc[nb][0] + bx, acc[nb][1] + by);
        if (rA + 8 < Nn)
            *(float2*)(Y + (size_t)(rA + 8) * 64 + col) = make_float2(acc[nb][2] + bx, acc[nb][3] + by);
    }
}

// ---------------- edge gather + normalized scatter-add ----------------
__global__ void __launch_bounds__(256) k_edge(
    const int4* __restrict__ pack, const float* __restrict__ xw,
    float* __restrict__ out, int E)
{
    int gid = blockIdx.x * blockDim.x + threadIdx.x;
    int e = gid >> 4;
    if (e >= E) return;
    int j = (gid & 15) << 2;

    const int4 p = __ldg(&pack[e]);
    const float inv = __int_as_float(p.z);

    const float4 v = __ldg((const float4*)(xw + p.x + j));
    float* addr = out + p.y + j;
    asm volatile("red.global.add.v4.f32 [%0], {%1,%2,%3,%4};"
                 :: "l"(addr), "f"(v.x * inv), "f"(v.y * inv), "f"(v.z * inv), "f"(v.w * inv)
                 : "memory");
}

// ---------------- launch ----------------
extern "C" void kernel_launch(void* const* d_in, const int* in_sizes, int n_in,
                              void* d_out, int out_size) {
    const float* x       = (const float*)d_in[0];
    const int*   ei      = (const int*)d_in[1];   // int32 (JAX x64 disabled)
    const int*   et      = (const int*)d_in[2];
    const float* W1_rel  = (const float*)d_in[3];
    const float* W1_root = (const float*)d_in[4];
    const float* b1      = (const float*)d_in[5];
    const float* W2_rel  = (const float*)d_in[6];
    const float* W2_root = (const float*)d_in[7];
    const float* b2      = (const float*)d_in[8];
    float* out = (float*)d_out;

    const int N = in_sizes[0] / INF;
    const int E = in_sizes[2];

    float *xw, *h;
    int *cnt;
    int4 *pack;
    __nv_bfloat16 *xhi, *xlo, *bh1, *bl1, *bh2, *bl2;
    cudaGetSymbolAddress((void**)&xw,   g_xw);
    cudaGetSymbolAddress((void**)&h,    g_h);
    cudaGetSymbolAddress((void**)&cnt,  g_cnt);
    cudaGetSymbolAddress((void**)&pack, g_epack);
    cudaGetSymbolAddress((void**)&xhi,  g_xhi);
    cudaGetSymbolAddress((void**)&xlo,  g_xlo);
    cudaGetSymbolAddress((void**)&bh1,  g_bhi1);
    cudaGetSymbolAddress((void**)&bl1,  g_blo1);
    cudaGetSymbolAddress((void**)&bh2,  g_bhi2);
    cudaGetSymbolAddress((void**)&bl2,  g_blo2);

    // dynamic smem: (2*128 + 2*64) * 72 bf16 elems * 2B = 55296 B (same both layers)
    const int SMB = (2 * 128 + 2 * 64) * 72 * 2;
    cudaFuncSetAttribute(k_mma<128>, cudaFuncAttributeMaxDynamicSharedMemorySize, SMB);
    cudaFuncSetAttribute(k_mma<64>,  cudaFuncAttributeMaxDynamicSharedMemorySize, SMB);

    // edge prep
    k_zero_cnt<<<(N * RREL + 255) / 256, 256>>>(cnt, N * RREL);
    k_count<<<(E + 255) / 256, 256>>>(ei, et, cnt, E);
    k_pack<<<(E + 255) / 256, 256>>>(ei, et, cnt, pack, E, N);

    // weight + input splits (layer 1)
    k_splitw<<<(9 * 64 * 128 + 255) / 256, 256>>>(W1_rel, W1_root, bh1, bl1, 128);
    k_split<false><<<(N * 128 / 4 + 255) / 256, 256>>>(x, xhi, xlo, N * 128);

    dim3 gg((N + 127) / 128, 9);
    long long tot = (long long)E * 16;
    int eb = (int)((tot + 255) / 256);

    // Layer 1
    k_mma<128><<<gg, 256, SMB>>>(xhi, xlo, bh1, bl1, b1, xw, h, N);
    k_edge<<<eb, 256>>>(pack, xw, h, E);

    // Layer 2 (ReLU fused into split)
    k_splitw<<<(9 * 64 * 64 + 255) / 256, 256>>>(W2_rel, W2_root, bh2, bl2, 64);
    k_split<true><<<(N * 64 / 4 + 255) / 256, 256>>>(h, xhi, xlo, N * 64);
    k_mma<64><<<gg, 256, SMB>>>(xhi, xlo, bh2, bl2, b2, xw, out, N);
    k_edge<<<eb, 256>>>(pack, xw, out, E);
}

// round 10
// speedup vs baseline: 2.6081x; 1.3615x over previous
#include <cuda_runtime.h>
#include <cuda_bf16.h>
#include <cstdint>

// Problem constants (shapes fixed by dataset)
#define NMAX  50000
#define EMAX  1600000
#define RREL  8
#define INF   128

// ---------------- scratch (static device globals; no allocs) ----------------
__device__ __align__(256) float g_xw[(size_t)RREL * NMAX * 64];
__device__ __align__(256) float g_h[(size_t)NMAX * 64];
__device__ __align__(256) int   g_cnt[NMAX * RREL];
__device__ __align__(256) int2  g_sp[EMAX];        // CSR-ordered {gatherOff, inv bits}
__device__ __align__(256) int   g_off[NMAX + 1];
__device__ __align__(256) int   g_cur[NMAX];
__device__ __align__(256) int   g_bsum[64];
__device__ __align__(256) __nv_bfloat16 g_xhi[(size_t)NMAX * INF];
__device__ __align__(256) __nv_bfloat16 g_xlo[(size_t)NMAX * INF];
__device__ __align__(256) __nv_bfloat16 g_bhi1[9 * 64 * 128];
__device__ __align__(256) __nv_bfloat16 g_blo1[9 * 64 * 128];
__device__ __align__(256) __nv_bfloat16 g_bhi2[9 * 64 * 64];
__device__ __align__(256) __nv_bfloat16 g_blo2[9 * 64 * 64];

__device__ __forceinline__ uint32_t smem_u32(const void* p) {
    uint32_t a;
    asm("{ .reg .u64 t; cvta.to.shared.u64 t, %1; cvt.u32.u64 %0, t; }" : "=r"(a) : "l"(p));
    return a;
}
__device__ __forceinline__ void ldsm4(uint32_t* r, uint32_t addr) {
    asm volatile("ldmatrix.sync.aligned.m8n8.x4.shared.b16 {%0,%1,%2,%3}, [%4];"
                 : "=r"(r[0]), "=r"(r[1]), "=r"(r[2]), "=r"(r[3]) : "r"(addr));
}
__device__ __forceinline__ void mma16816(float* c, const uint32_t* a, uint32_t b0, uint32_t b1) {
    asm volatile(
        "mma.sync.aligned.m16n8k16.row.col.f32.bf16.bf16.f32 "
        "{%0,%1,%2,%3}, {%4,%5,%6,%7}, {%8,%9}, {%0,%1,%2,%3};"
        : "+f"(c[0]), "+f"(c[1]), "+f"(c[2]), "+f"(c[3])
        : "r"(a[0]), "r"(a[1]), "r"(a[2]), "r"(a[3]), "r"(b0), "r"(b1));
}

// ---------------- prep: counts ----------------
__global__ void k_zero_cnt(int* __restrict__ cnt, int n) {
    int i = blockIdx.x * blockDim.x + threadIdx.x;
    if (i < n) cnt[i] = 0;
}
__global__ void k_count(const int* __restrict__ ei, const int* __restrict__ et,
                        int* __restrict__ cnt, int E) {
    int e = blockIdx.x * blockDim.x + threadIdx.x;
    if (e >= E) return;
    atomicAdd(&cnt[ei[E + e] * RREL + et[e]], 1);
}

// ---------------- prep: exclusive scan of per-dst degrees (3 kernels) ----------------
__global__ void k_scan_a(const int* __restrict__ cnt, int* __restrict__ off,
                         int* __restrict__ bsum, int N) {
    __shared__ int s[1024];
    int d = blockIdx.x * 1024 + threadIdx.x;
    int deg = 0;
    if (d < N) {
        int4 a = ((const int4*)cnt)[d * 2];
        int4 b = ((const int4*)cnt)[d * 2 + 1];
        deg = a.x + a.y + a.z + a.w + b.x + b.y + b.z + b.w;
    }
    s[threadIdx.x] = deg;
    __syncthreads();
    for (int o = 1; o < 1024; o <<= 1) {
        int v = (threadIdx.x >= o) ? s[threadIdx.x - o] : 0;
        __syncthreads();
        s[threadIdx.x] += v;
        __syncthreads();
    }
    if (d < N) off[d] = s[threadIdx.x] - deg;   // exclusive within block
    if (threadIdx.x == 1023) bsum[blockIdx.x] = s[1023];
}
__global__ void k_scan_b(int* __restrict__ bsum, int nb, int* __restrict__ off, int N) {
    __shared__ int s[64];
    int v = (threadIdx.x < nb) ? bsum[threadIdx.x] : 0;
    s[threadIdx.x] = v;
    __syncthreads();
    for (int o = 1; o < 64; o <<= 1) {
        int u = (threadIdx.x >= o) ? s[threadIdx.x - o] : 0;
        __syncthreads();
        s[threadIdx.x] += u;
        __syncthreads();
    }
    if (threadIdx.x < nb) bsum[threadIdx.x] = s[threadIdx.x] - v;  // exclusive base
    if (threadIdx.x == 63) off[N] = s[63];
}
__global__ void k_scan_c(int* __restrict__ off, int* __restrict__ cur,
                         const int* __restrict__ bsum, int N) {
    int d = blockIdx.x * 1024 + threadIdx.x;
    if (d >= N) return;
    int o = off[d] + bsum[blockIdx.x];
    off[d] = o;
    cur[d] = o;
}

// ---------------- prep: permute edges into dst-CSR order ----------------
__global__ void k_permute(const int* __restrict__ ei, const int* __restrict__ et,
                          const int* __restrict__ cnt, int* __restrict__ cur,
                          int2* __restrict__ sp, int E, int Nn) {
    int e = blockIdx.x * blockDim.x + threadIdx.x;
    if (e >= E) return;
    int s = ei[e];
    int d = ei[E + e];
    int t = et[e];
    int c = cnt[d * RREL + t];
    float inv = 1.0f / (float)(c > 0 ? c : 1);
    int pos = atomicAdd(&cur[d], 1);
    sp[pos] = make_int2((t * Nn + s) * 64, __float_as_int(inv));
}

// ---------------- fp32 -> bf16 hi/lo split (optionally fused ReLU) ----------------
template<bool RELU>
__global__ void k_split(const float* __restrict__ src, __nv_bfloat16* __restrict__ hi,
                        __nv_bfloat16* __restrict__ lo, int n) {
    int i = blockIdx.x * blockDim.x + threadIdx.x;
    int i4 = i * 4;
    if (i4 >= n) return;
    float4 v = *(const float4*)(src + i4);
    if (RELU) {
        v.x = fmaxf(v.x, 0.f); v.y = fmaxf(v.y, 0.f);
        v.z = fmaxf(v.z, 0.f); v.w = fmaxf(v.w, 0.f);
    }
    float vv[4] = {v.x, v.y, v.z, v.w};
    __nv_bfloat16 h[4], l[4];
#pragma unroll
    for (int j = 0; j < 4; j++) {
        h[j] = __float2bfloat16_rn(vv[j]);
        l[j] = __float2bfloat16_rn(vv[j] - __bfloat162float(h[j]));
    }
    ((__nv_bfloat162*)hi)[i * 2]     = __nv_bfloat162(h[0], h[1]);
    ((__nv_bfloat162*)hi)[i * 2 + 1] = __nv_bfloat162(h[2], h[3]);
    ((__nv_bfloat162*)lo)[i * 2]     = __nv_bfloat162(l[0], l[1]);
    ((__nv_bfloat162*)lo)[i * 2 + 1] = __nv_bfloat162(l[2], l[3]);
}

// ---------------- weight transpose+split: Bt[m][n][k] = W_m[k][n] ----------------
__global__ void k_splitw(const float* __restrict__ Wrel, const float* __restrict__ Wroot,
                         __nv_bfloat16* __restrict__ hi, __nv_bfloat16* __restrict__ lo, int K) {
    int idx = blockIdx.x * blockDim.x + threadIdx.x;
    if (idx >= 9 * 64 * K) return;
    int m = idx / (64 * K);
    int r = idx % (64 * K);
    int n = r / K;
    int k = r % K;
    float w = (m < RREL) ? Wrel[(size_t)m * K * 64 + k * 64 + n] : Wroot[k * 64 + n];
    __nv_bfloat16 h = __float2bfloat16_rn(w);
    hi[idx] = h;
    lo[idx] = __float2bfloat16_rn(w - __bfloat162float(h));
}

// ---------------- HMMA batched skinny GEMM (mma.sync, bf16 3-term split) --------
template<int K>
__global__ void __launch_bounds__(256) k_mma(
    const __nv_bfloat16* __restrict__ Ahi, const __nv_bfloat16* __restrict__ Alo,
    const __nv_bfloat16* __restrict__ Bhi, const __nv_bfloat16* __restrict__ Blo,
    const float* __restrict__ bias, float* __restrict__ Yrel, float* __restrict__ Yroot,
    int Nn)
{
    constexpr int KC  = 64;
    constexpr int LDB = KC + 8;                 // 72 bf16 = 144B row stride
    constexpr int NCH = K / KC;
    constexpr int OAH = 0;
    constexpr int OAL = 128 * LDB;
    constexpr int OBH = 2 * 128 * LDB;
    constexpr int OBL = 2 * 128 * LDB + 64 * LDB;

    extern __shared__ __nv_bfloat16 sm[];
    const uint32_t sb = smem_u32(sm);
    const int tid = threadIdx.x;
    const int w   = tid >> 5;
    const int l   = tid & 31;
    const int m   = blockIdx.y;
    const int row0 = blockIdx.x * 128;

    const __nv_bfloat16* bh = Bhi + (size_t)m * 64 * K;
    const __nv_bfloat16* bl = Blo + (size_t)m * 64 * K;

    const int arow = w * 16 + (l & 15);
    const int acol = (l >> 4) << 3;
    const uint32_t aoffA = (uint32_t)(arow * LDB + acol) * 2;
    const int brow = (l & 7) + ((l >> 4) << 3);
    const int bcol = ((l >> 3) & 1) << 3;
    const uint32_t aoffB = (uint32_t)(brow * LDB + bcol) * 2;

    float acc[8][4];
#pragma unroll
    for (int nb = 0; nb < 8; nb++)
#pragma unroll
        for (int j = 0; j < 4; j++) acc[nb][j] = 0.f;

    for (int kc = 0; kc < NCH; ++kc) {
        if (kc) __syncthreads();
#pragma unroll
        for (int it = 0; it < 4; ++it) {
            int idx = tid + it * 256;
            int r = idx >> 3, c8 = (idx & 7) << 3;
            int grow = row0 + r;
            uint4 vh = make_uint4(0, 0, 0, 0), vl = make_uint4(0, 0, 0, 0);
            if (grow < Nn) {
                vh = *(const uint4*)(Ahi + (size_t)grow * K + kc * KC + c8);
                vl = *(const uint4*)(Alo + (size_t)grow * K + kc * KC + c8);
            }
            *(uint4*)&sm[OAH + r * LDB + c8] = vh;
            *(uint4*)&sm[OAL + r * LDB + c8] = vl;
        }
#pragma unroll
        for (int it = 0; it < 2; ++it) {
            int idx = tid + it * 256;
            int r = idx >> 3, c8 = (idx & 7) << 3;
            *(uint4*)&sm[OBH + r * LDB + c8] = *(const uint4*)(bh + (size_t)r * K + kc * KC + c8);
            *(uint4*)&sm[OBL + r * LDB + c8] = *(const uint4*)(bl + (size_t)r * K + kc * KC + c8);
        }
        __syncthreads();

#pragma unroll
        for (int ks = 0; ks < KC / 16; ++ks) {
            const uint32_t kb = ks * 32;
            uint32_t ah[4], al[4];
            ldsm4(ah, sb + (OAH * 2) + aoffA + kb);
            ldsm4(al, sb + (OAL * 2) + aoffA + kb);
#pragma unroll
            for (int p = 0; p < 4; ++p) {
                uint32_t bhf[4], blf[4];
                const uint32_t bo = (uint32_t)(p * 16 * LDB) * 2 + kb;
                ldsm4(bhf, sb + (OBH * 2) + aoffB + bo);
                ldsm4(blf, sb + (OBL * 2) + aoffB + bo);
                mma16816(acc[2 * p],     ah, bhf[0], bhf[1]);
                mma16816(acc[2 * p + 1], ah, bhf[2], bhf[3]);
                mma16816(acc[2 * p],     ah, blf[0], blf[1]);
                mma16816(acc[2 * p + 1], ah, blf[2], blf[3]);
                mma16816(acc[2 * p],     al, bhf[0], bhf[1]);
                mma16816(acc[2 * p + 1], al, bhf[2], bhf[3]);
            }
        }
    }

    float* Y = (m < RREL) ? (Yrel + (size_t)m * Nn * 64) : Yroot;
    const bool useBias = (m == RREL);
    const int rA = row0 + w * 16 + (l >> 2);
    const int c0 = (l & 3) * 2;
#pragma unroll
    for (int nb = 0; nb < 8; ++nb) {
        int col = nb * 8 + c0;
        float bx = 0.f, by = 0.f;
        if (useBias) { bx = bias[col]; by = bias[col + 1]; }
        if (rA < Nn)
            *(float2*)(Y + (size_t)rA * 64 + col) = make_float2(acc[nb][0] + bx, acc[nb][1] + by);
        if (rA + 8 < Nn)
            *(float2*)(Y + (size_t)(rA + 8) * 64 + col) = make_float2(acc[nb][2] + bx, acc[nb][3] + by);
    }
}

// ---------------- CSR aggregation (no atomics) ----------------
// 16 lanes per dst (each owns a float4 column slice); loop the dst's contiguous
// edge slice; accumulate in registers; RMW the root-initialized output once.
__global__ void __launch_bounds__(256) k_agg(
    const int* __restrict__ off, const int2* __restrict__ sp,
    const float* __restrict__ xw, float* __restrict__ out, int Nn)
{
    int d = blockIdx.x * 16 + (threadIdx.x >> 4);
    if (d >= Nn) return;
    int lane = (threadIdx.x & 15) << 2;

    int beg = __ldg(&off[d]);
    int end = __ldg(&off[d + 1]);

    float* yp = out + (size_t)d * 64 + lane;
    float4 acc = *(float4*)yp;

    int e = beg;
    for (; e + 1 < end; e += 2) {
        int2 p0 = __ldg(&sp[e]);
        int2 p1 = __ldg(&sp[e + 1]);
        float4 v0 = __ldg((const float4*)(xw + p0.x + lane));
        float4 v1 = __ldg((const float4*)(xw + p1.x + lane));
        float i0 = __int_as_float(p0.y), i1 = __int_as_float(p1.y);
        acc.x = fmaf(v0.x, i0, acc.x); acc.y = fmaf(v0.y, i0, acc.y);
        acc.z = fmaf(v0.z, i0, acc.z); acc.w = fmaf(v0.w, i0, acc.w);
        acc.x = fmaf(v1.x, i1, acc.x); acc.y = fmaf(v1.y, i1, acc.y);
        acc.z = fmaf(v1.z, i1, acc.z); acc.w = fmaf(v1.w, i1, acc.w);
    }
    if (e < end) {
        int2 p = __ldg(&sp[e]);
        float4 v = __ldg((const float4*)(xw + p.x + lane));
        float iv = __int_as_float(p.y);
        acc.x = fmaf(v.x, iv, acc.x); acc.y = fmaf(v.y, iv, acc.y);
        acc.z = fmaf(v.z, iv, acc.z); acc.w = fmaf(v.w, iv, acc.w);
    }
    *(float4*)yp = acc;
}

// ---------------- launch ----------------
extern "C" void kernel_launch(void* const* d_in, const int* in_sizes, int n_in,
                              void* d_out, int out_size) {
    const float* x       = (const float*)d_in[0];
    const int*   ei      = (const int*)d_in[1];   // int32 (JAX x64 disabled)
    const int*   et      = (const int*)d_in[2];
    const float* W1_rel  = (const float*)d_in[3];
    const float* W1_root = (const float*)d_in[4];
    const float* b1      = (const float*)d_in[5];
    const float* W2_rel  = (const float*)d_in[6];
    const float* W2_root = (const float*)d_in[7];
    const float* b2      = (const float*)d_in[8];
    float* out = (float*)d_out;

    const int N = in_sizes[0] / INF;
    const int E = in_sizes[2];

    float *xw, *h;
    int *cnt, *offp, *curp, *bsum;
    int2 *sp;
    __nv_bfloat16 *xhi, *xlo, *bh1, *bl1, *bh2, *bl2;
    cudaGetSymbolAddress((void**)&xw,   g_xw);
    cudaGetSymbolAddress((void**)&h,    g_h);
    cudaGetSymbolAddress((void**)&cnt,  g_cnt);
    cudaGetSymbolAddress((void**)&sp,   g_sp);
    cudaGetSymbolAddress((void**)&offp, g_off);
    cudaGetSymbolAddress((void**)&curp, g_cur);
    cudaGetSymbolAddress((void**)&bsum, g_bsum);
    cudaGetSymbolAddress((void**)&xhi,  g_xhi);
    cudaGetSymbolAddress((void**)&xlo,  g_xlo);
    cudaGetSymbolAddress((void**)&bh1,  g_bhi1);
    cudaGetSymbolAddress((void**)&bl1,  g_blo1);
    cudaGetSymbolAddress((void**)&bh2,  g_bhi2);
    cudaGetSymbolAddress((void**)&bl2,  g_blo2);

    const int SMB = (2 * 128 + 2 * 64) * 72 * 2;  // 55296 B
    cudaFuncSetAttribute(k_mma<128>, cudaFuncAttributeMaxDynamicSharedMemorySize, SMB);
    cudaFuncSetAttribute(k_mma<64>,  cudaFuncAttributeMaxDynamicSharedMemorySize, SMB);

    const int nscan = (N + 1023) / 1024;

    // ---- CSR build (once; reused by both layers) ----
    k_zero_cnt<<<(N * RREL + 255) / 256, 256>>>(cnt, N * RREL);
    k_count<<<(E + 255) / 256, 256>>>(ei, et, cnt, E);
    k_scan_a<<<nscan, 1024>>>(cnt, offp, bsum, N);
    k_scan_b<<<1, 64>>>(bsum, nscan, offp, N);
    k_scan_c<<<nscan, 1024>>>(offp, curp, bsum, N);
    k_permute<<<(E + 255) / 256, 256>>>(ei, et, cnt, curp, sp, E, N);

    // ---- weight + input splits (layer 1) ----
    k_splitw<<<(9 * 64 * 128 + 255) / 256, 256>>>(W1_rel, W1_root, bh1, bl1, 128);
    k_split<false><<<(N * 128 / 4 + 255) / 256, 256>>>(x, xhi, xlo, N * 128);

    dim3 gg((N + 127) / 128, 9);
    const int ab = (N + 15) / 16;

    // Layer 1: transforms (+ root+bias init of h), then CSR aggregation into h
    k_mma<128><<<gg, 256, SMB>>>(xhi, xlo, bh1, bl1, b1, xw, h, N);
    k_agg<<<ab, 256>>>(offp, sp, xw, h, N);

    // Layer 2 (ReLU fused into split); root init of d_out; CSR aggregation into d_out
    k_splitw<<<(9 * 64 * 64 + 255) / 256, 256>>>(W2_rel, W2_root, bh2, bl2, 64);
    k_split<true><<<(N * 64 / 4 + 255) / 256, 256>>>(h, xhi, xlo, N * 64);
    k_mma<64><<<gg, 256, SMB>>>(xhi, xlo, bh2, bl2, b2, xw, out, N);
    k_agg<<<ab, 256>>>(offp, sp, xw, out, N);
}